// round 6
// baseline (speedup 1.0000x reference)
#include <cuda_runtime.h>
#include <cuda_bf16.h>

#define BB     128
#define NTOK   1369
#define DINOD  384
#define CLIPD  512
#define NH     8
#define ROWS   36
#define CHUNKS 39                       // ceil(1369/36)
#define CHUNK_FLOATS (ROWS*DINOD)       // 13824
// dynamic smem for k3: 2 buffers + lg(288) + w_s(288) + r_s(8) + m_s(8)
#define SMEM3 ((2*CHUNK_FLOATS + 2*ROWS*NH + 16)*4)

__device__ __align__(16) float g_Q[BB*CLIPD];
__device__ __align__(16) float g_qk[BB*NH*DINOD];
__device__ __align__(16) float g_ctx[BB*NH*DINOD];

// ---- packed f32x2 helpers ----
__device__ __forceinline__ unsigned long long pk2(float x, float y){
  unsigned long long r; asm("mov.b64 %0, {%1,%2};" : "=l"(r) : "f"(x), "f"(y)); return r;
}
__device__ __forceinline__ float2 upk2(unsigned long long v){
  float2 r; asm("mov.b64 {%0,%1}, %2;" : "=f"(r.x), "=f"(r.y) : "l"(v)); return r;
}
__device__ __forceinline__ void fma2(unsigned long long& d, unsigned long long a, unsigned long long b){
  asm("fma.rn.f32x2 %0, %1, %2, %0;" : "+l"(d) : "l"(a), "l"(b));
}
__device__ __forceinline__ void mul2(unsigned long long& d, unsigned long long a){
  asm("mul.rn.f32x2 %0, %0, %1;" : "+l"(d) : "l"(a));
}
__device__ __forceinline__ void cp16z(float* dst, const float* src, int sz){
  unsigned sa = (unsigned)__cvta_generic_to_shared(dst);
  asm volatile("cp.async.cg.shared.global [%0], [%1], 16, %2;" :: "r"(sa), "l"(src), "r"(sz) : "memory");
}

// ============ K1: Q = clip @ Wq + bq ============
__global__ void __launch_bounds__(512) k1_qproj(const float* __restrict__ clip,
                                                const float* __restrict__ Wq,
                                                const float* __restrict__ bq){
  __shared__ float cs[2][CLIPD];
  int t = threadIdx.x;
  int b0 = blockIdx.x * 2;
  cs[0][t] = clip[(size_t)b0*CLIPD + t];
  cs[1][t] = clip[(size_t)(b0+1)*CLIPD + t];
  __syncthreads();
  float a0 = bq[t], a1 = a0;
  #pragma unroll 8
  for(int c = 0; c < CLIPD; c++){
    float w = Wq[(size_t)c*CLIPD + t];
    a0 = fmaf(cs[0][c], w, a0);
    a1 = fmaf(cs[1][c], w, a1);
  }
  g_Q[(size_t)b0*CLIPD + t]     = a0;
  g_Q[(size_t)(b0+1)*CLIPD + t] = a1;
}

// ============ K2: qk[b,h,c] = sum_d Wk[c,h*64+d]*Q[b,h*64+d] / (8*temp) ============
__global__ void __launch_bounds__(384) k2_qk(const float* __restrict__ Wk,
                                             const float* __restrict__ temp){
  __shared__ float Qs[4][CLIPD];
  int t = threadIdx.x;
  int b0 = blockIdx.x * 4;
  for(int i = t; i < 4*CLIPD; i += 384) Qs[i>>9][i&511] = g_Q[(size_t)b0*CLIPD + i];
  __syncthreads();
  float inv_scale = 1.0f/(8.0f*temp[0]);
  int w = t>>5, l = t&31;
  for(int c = w; c < DINOD; c += 12){
    const float* wr = Wk + (size_t)c*CLIPD;
    #pragma unroll
    for(int h = 0; h < NH; h++){
      float w0 = wr[h*64 + l], w1 = wr[h*64 + 32 + l];
      #pragma unroll
      for(int bb = 0; bb < 4; bb++){
        float s = w0*Qs[bb][h*64+l] + w1*Qs[bb][h*64+32+l];
        #pragma unroll
        for(int o = 16; o; o >>= 1) s += __shfl_xor_sync(0xffffffffu, s, o);
        if(l == 0) g_qk[((size_t)(b0+bb)*NH + h)*DINOD + c] = s*inv_scale;
      }
    }
  }
}

// ============ K3: streaming single-query attention, one block per batch ============
__global__ void __launch_bounds__(384, 1) k3_attn(const float* __restrict__ dino){
  extern __shared__ float sm[];
  float* dbuf = sm;                          // 2 * 13824
  float* lg   = sm + 2*CHUNK_FLOATS;         // 288
  float* w_s  = lg + ROWS*NH;                // 288
  float* r_s  = w_s + ROWS*NH;               // 8
  float* m_s  = r_s + 8;                     // 8

  int t = threadIdx.x;
  int wid = t>>5, lane = t&31;
  int b = blockIdx.x;
  const float* dino_b = dino + (size_t)b*NTOK*DINOD;
  const long limitf = (long)NTOK*DINOD;

  // qk in registers, packed: c = j*128 + lane*4 + {0..3}
  unsigned long long qkp[NH][3][2];
  {
    const float* qkb = g_qk + (size_t)b*NH*DINOD;
    #pragma unroll
    for(int h = 0; h < NH; h++)
      #pragma unroll
      for(int j = 0; j < 3; j++){
        float4 v = *(const float4*)(qkb + h*DINOD + j*128 + lane*4);
        qkp[h][j][0] = pk2(v.x, v.y);
        qkp[h][j][1] = pk2(v.z, v.w);
      }
  }

  unsigned long long c0=0ull, c1=0ull, c2=0ull, c3=0ull; // ctx col t, head pairs
  float m_reg = -1e30f, l_run = 0.0f;                    // valid for t < 8

  // prologue: chunk 0
  #pragma unroll
  for(int k = 0; k < 9; k++){
    int gi = t + k*384;
    long f = (long)gi*4;
    cp16z(dbuf + gi*4, dino_b + f, (f+4 <= limitf) ? 16 : 0);
  }
  asm volatile("cp.async.commit_group;" ::: "memory");

  for(int i = 0; i < CHUNKS; i++){
    __syncthreads();                    // buffers/w_s free (prev phase B done)
    if(i+1 < CHUNKS){
      float* dst = dbuf + ((i+1)&1)*CHUNK_FLOATS;
      long basef = (long)(i+1)*CHUNK_FLOATS;
      #pragma unroll
      for(int k = 0; k < 9; k++){
        int gi = t + k*384;
        long f = basef + (long)gi*4;
        cp16z(dst + gi*4, dino_b + f, (f+4 <= limitf) ? 16 : 0);
      }
    }
    asm volatile("cp.async.commit_group;" ::: "memory"); // (possibly empty)
    asm volatile("cp.async.wait_group 1;" ::: "memory"); // chunk i landed
    __syncthreads();

    const float* dcur = dbuf + (i&1)*CHUNK_FLOATS;
    int base = i*ROWS;

    // ---- Phase A: logits; warp handles 3 rows x 8 heads ----
    #pragma unroll
    for(int rr = 0; rr < 3; rr++){
      int row = wid*3 + rr;
      if(base + row < NTOK){
        const float4* rf = (const float4*)(dcur + row*DINOD);
        float4 va = rf[lane], vb = rf[32+lane], vc = rf[64+lane];
        unsigned long long d0 = pk2(va.x,va.y), d1 = pk2(va.z,va.w),
                           d2 = pk2(vb.x,vb.y), d3 = pk2(vb.z,vb.w),
                           d4 = pk2(vc.x,vc.y), d5 = pk2(vc.z,vc.w);
        #pragma unroll
        for(int h = 0; h < NH; h++){
          unsigned long long acc = 0ull;
          fma2(acc, d0, qkp[h][0][0]); fma2(acc, d1, qkp[h][0][1]);
          fma2(acc, d2, qkp[h][1][0]); fma2(acc, d3, qkp[h][1][1]);
          fma2(acc, d4, qkp[h][2][0]); fma2(acc, d5, qkp[h][2][1]);
          float2 p = upk2(acc);
          float s = p.x + p.y;
          #pragma unroll
          for(int o = 16; o; o >>= 1) s += __shfl_xor_sync(0xffffffffu, s, o);
          if(lane == 0) lg[row*NH + h] = s;
        }
      } else if(lane < NH){
        lg[row*NH + lane] = -1e30f;
      }
    }
    __syncthreads();
    // ---- per-head max / rescale (thread h) ----
    if(t < NH){
      float mx = -1e30f;
      #pragma unroll 6
      for(int n = 0; n < ROWS; n++) mx = fmaxf(mx, lg[n*NH + t]);
      float mn = fmaxf(m_reg, mx);
      r_s[t] = __expf(m_reg - mn);
      m_s[t] = mn;
      m_reg = mn;
    }
    __syncthreads();
    if(t < ROWS*NH) w_s[t] = __expf(lg[t] - m_s[t & 7]);
    __syncthreads();
    // ---- Phase B: ctx update, thread owns dino column c = t ----
    {
      ulonglong2 ra = *(const ulonglong2*)r_s;
      ulonglong2 rb = *(const ulonglong2*)(r_s + 4);
      mul2(c0, ra.x); mul2(c1, ra.y); mul2(c2, rb.x); mul2(c3, rb.y);
      #pragma unroll 4
      for(int n = 0; n < ROWS; n++){
        float dv = dcur[n*DINOD + t];
        unsigned long long dd = pk2(dv, dv);
        ulonglong2 wa = *(const ulonglong2*)(w_s + n*NH);
        ulonglong2 wb = *(const ulonglong2*)(w_s + n*NH + 4);
        fma2(c0, wa.x, dd); fma2(c1, wa.y, dd);
        fma2(c2, wb.x, dd); fma2(c3, wb.y, dd);
      }
      if(t < NH){
        float acc = 0.0f;
        #pragma unroll 6
        for(int n = 0; n < ROWS; n++) acc += w_s[n*NH + t];
        l_run = l_run * r_s[t] + acc;
      }
    }
  }

  if(t < NH) m_s[t] = 1.0f / l_run;   // reuse m_s as inverse denom
  __syncthreads();
  float* cb = g_ctx + (size_t)b*NH*DINOD;
  float2 p0 = upk2(c0), p1 = upk2(c1), p2 = upk2(c2), p3 = upk2(c3);
  cb[0*DINOD + t] = p0.x*m_s[0];
  cb[1*DINOD + t] = p0.y*m_s[1];
  cb[2*DINOD + t] = p1.x*m_s[2];
  cb[3*DINOD + t] = p1.y*m_s[3];
  cb[4*DINOD + t] = p2.x*m_s[4];
  cb[5*DINOD + t] = p2.y*m_s[5];
  cb[6*DINOD + t] = p3.x*m_s[6];
  cb[7*DINOD + t] = p3.y*m_s[7];
}

// ============ K4: out = ctx @ Wv + bv, then LayerNorm ============
__global__ void __launch_bounds__(512) k4_out(const float* __restrict__ Wv,
                                              const float* __restrict__ bv,
                                              const float* __restrict__ gamma,
                                              const float* __restrict__ beta,
                                              float* __restrict__ out){
  __shared__ float cs[2][NH*DINOD];
  __shared__ float red[4][16];
  int t = threadIdx.x;
  int b0 = blockIdx.x * 2;
  for(int i = t; i < NH*DINOD; i += 512){
    cs[0][i] = g_ctx[(size_t)b0*NH*DINOD + i];
    cs[1][i] = g_ctx[(size_t)(b0+1)*NH*DINOD + i];
  }
  __syncthreads();
  int h = t>>6;
  const float* p0 = cs[0] + h*DINOD;
  const float* p1 = cs[1] + h*DINOD;
  float a0 = bv[t], a1 = a0;
  #pragma unroll 8
  for(int c = 0; c < DINOD; c++){
    float wv = Wv[(size_t)c*CLIPD + t];
    a0 = fmaf(p0[c], wv, a0);
    a1 = fmaf(p1[c], wv, a1);
  }
  float s0 = a0, q0 = a0*a0, s1 = a1, q1 = a1*a1;
  #pragma unroll
  for(int o = 16; o; o >>= 1){
    s0 += __shfl_xor_sync(0xffffffffu, s0, o);
    q0 += __shfl_xor_sync(0xffffffffu, q0, o);
    s1 += __shfl_xor_sync(0xffffffffu, s1, o);
    q1 += __shfl_xor_sync(0xffffffffu, q1, o);
  }
  int wid = t>>5, lane = t&31;
  if(lane == 0){ red[0][wid]=s0; red[1][wid]=q0; red[2][wid]=s1; red[3][wid]=q1; }
  __syncthreads();
  if(t < 4){
    float s = 0.0f;
    #pragma unroll
    for(int i = 0; i < 16; i++) s += red[t][i];
    red[t][0] = s;
  }
  __syncthreads();
  float mu0 = red[0][0]*(1.0f/512.0f);
  float v0  = red[1][0]*(1.0f/512.0f) - mu0*mu0;
  float mu1 = red[2][0]*(1.0f/512.0f);
  float v1  = red[3][0]*(1.0f/512.0f) - mu1*mu1;
  float rs0 = rsqrtf(v0 + 1e-5f), rs1 = rsqrtf(v1 + 1e-5f);
  float g = gamma[t], be = beta[t];
  out[(size_t)b0*CLIPD + t]     = (a0 - mu0)*rs0*g + be;
  out[(size_t)(b0+1)*CLIPD + t] = (a1 - mu1)*rs1*g + be;
}

extern "C" void kernel_launch(void* const* d_in, const int* in_sizes, int n_in,
                              void* d_out, int out_size) {
  const float* dino  = (const float*)d_in[0];
  const float* clip  = (const float*)d_in[1];
  const float* Wq    = (const float*)d_in[2];
  const float* bq    = (const float*)d_in[3];
  const float* Wk    = (const float*)d_in[4];
  // d_in[5] = bk: cancels in softmax, unused
  const float* Wv    = (const float*)d_in[6];
  const float* bv    = (const float*)d_in[7];
  const float* temp  = (const float*)d_in[8];
  const float* gamma = (const float*)d_in[9];
  const float* beta  = (const float*)d_in[10];
  float* out = (float*)d_out;

  static int smem_set = 0;
  if(!smem_set){
    cudaFuncSetAttribute(k3_attn, cudaFuncAttributeMaxDynamicSharedMemorySize, SMEM3);
    smem_set = 1;
  }

  k1_qproj<<<BB/2, 512>>>(clip, Wq, bq);
  k2_qk<<<BB/4, 384>>>(Wk, temp);
  k3_attn<<<BB, 384, SMEM3>>>(dino);
  k4_out<<<BB/2, 512>>>(Wv, bv, gamma, beta, out);
}